// round 1
// baseline (speedup 1.0000x reference)
#include <cuda_runtime.h>
#include <math.h>

#define BB 2
#define LL 2048
#define HH 8
#define DH 64
#define HID 512
#define QKVP 3584
#define VP 2560
#define TOK (BB*LL)

// ---- static scratch (no allocations allowed) ----
__device__ float g_xt[TOK * HID];              // 8 MB   transformed features
__device__ float g_scan[BB * 64 * LL];         // 1 MB   scan channels, [b][c][l]
__device__ float g_proj[(size_t)TOK * QKVP];   // 56 MB  q|k|v|p
__device__ float g_xo[(size_t)TOK * VP];       // 40 MB  [o | gelu(p)]

// ============================================================
// 1) LayerNorm + feature scatter
// ============================================================
__global__ __launch_bounds__(128) void ln_kernel(const float* __restrict__ x,
                                                 const float* __restrict__ gamma,
                                                 const float* __restrict__ beta)
{
    int tok = blockIdx.x;
    int b = tok / LL, l = tok % LL;
    int t = threadIdx.x;

    float4 v = reinterpret_cast<const float4*>(x + (size_t)tok * HID)[t];
    float s  = v.x + v.y + v.z + v.w;
    float s2 = v.x*v.x + v.y*v.y + v.z*v.z + v.w*v.w;
    #pragma unroll
    for (int o = 16; o; o >>= 1) {
        s  += __shfl_xor_sync(0xffffffffu, s,  o);
        s2 += __shfl_xor_sync(0xffffffffu, s2, o);
    }
    __shared__ float red[8];
    __shared__ float stats[2];
    int w = t >> 5;
    if ((t & 31) == 0) { red[w] = s; red[4 + w] = s2; }
    __syncthreads();
    if (t == 0) {
        float ts  = red[0] + red[1] + red[2] + red[3];
        float ts2 = red[4] + red[5] + red[6] + red[7];
        float mu  = ts * (1.f / HID);
        float var = ts2 * (1.f / HID) - mu * mu;
        stats[0] = mu;
        stats[1] = rsqrtf(var + 1e-5f);
    }
    __syncthreads();
    float mu = stats[0], rstd = stats[1];

    float4 g  = reinterpret_cast<const float4*>(gamma)[t];
    float4 be = reinterpret_cast<const float4*>(beta)[t];
    float4 xn;
    xn.x = (v.x - mu) * rstd * g.x + be.x;
    xn.y = (v.y - mu) * rstd * g.y + be.y;
    xn.z = (v.z - mu) * rstd * g.z + be.z;
    xn.w = (v.w - mu) * rstd * g.w + be.w;

    int c0 = t * 4;
    if (c0 < 320) {
        *reinterpret_cast<float4*>(g_xt + (size_t)tok * HID + c0) = xn;
    } else if (c0 < 384) {
        int cc = c0 - 320;
        g_scan[((size_t)b * 64 + cc + 0) * LL + l] = xn.x;
        g_scan[((size_t)b * 64 + cc + 1) * LL + l] = xn.y;
        g_scan[((size_t)b * 64 + cc + 2) * LL + l] = xn.z;
        g_scan[((size_t)b * 64 + cc + 3) * LL + l] = xn.w;
    } else if (c0 < 448) {
        // shift by 1: xt[l+1] = xn[l]
        if (l + 1 < LL)
            *reinterpret_cast<float4*>(g_xt + (size_t)(tok + 1) * HID + c0) = xn;
        if (l == 0) {
            float4 z = make_float4(0.f, 0.f, 0.f, 0.f);
            *reinterpret_cast<float4*>(g_xt + (size_t)tok * HID + c0) = z;
        }
    } else {
        // shift by 2: xt[l+2] = xn[l]
        if (l + 2 < LL)
            *reinterpret_cast<float4*>(g_xt + (size_t)(tok + 2) * HID + c0) = xn;
        if (l == 0) {
            float4 z = make_float4(0.f, 0.f, 0.f, 0.f);
            *reinterpret_cast<float4*>(g_xt + (size_t)tok * HID + c0) = z;
            *reinterpret_cast<float4*>(g_xt + (size_t)(tok + 1) * HID + c0) = z;
        }
    }
}

// ============================================================
// 2) cumlogsumexp scan: one warp per (b, channel)
//    spm[l] = (M + log( cumsum(exp(5*x - M)) )) / 5
// ============================================================
__global__ __launch_bounds__(128) void scan_kernel()
{
    int wglob = blockIdx.x * 4 + (threadIdx.x >> 5);  // 0..127
    int lane  = threadIdx.x & 31;
    int b = wglob >> 6, c = wglob & 63;
    const float* src = g_scan + ((size_t)b * 64 + c) * LL;

    float M = -1e30f;
    for (int i = lane; i < LL; i += 32) M = fmaxf(M, src[i] * 5.f);
    #pragma unroll
    for (int o = 16; o; o >>= 1) M = fmaxf(M, __shfl_xor_sync(0xffffffffu, M, o));

    float carry = 0.f;
    float* dst = g_xt + 320 + c;
    for (int i0 = 0; i0 < LL; i0 += 32) {
        float e = expf(src[i0 + lane] * 5.f - M);
        float sc = e;
        #pragma unroll
        for (int o = 1; o < 32; o <<= 1) {
            float n = __shfl_up_sync(0xffffffffu, sc, o);
            if (lane >= o) sc += n;
        }
        float val = (M + logf(carry + sc)) * 0.2f;
        dst[(size_t)(b * LL + i0 + lane) * HID] = val;
        carry += __shfl_sync(0xffffffffu, sc, 31);
    }
}

// ============================================================
// 3) tiled SGEMM: C[M,N] = A[M,K] @ B[K,N] (+bias), 128x128x16
// ============================================================
#define BM 128
#define BN 128
#define BKK 16
__global__ __launch_bounds__(256) void sgemm(const float* __restrict__ A,
                                             const float* __restrict__ Bm,
                                             const float* __restrict__ bias,
                                             float* __restrict__ C,
                                             int M, int N, int K)
{
    __shared__ float As[BKK][BM];
    __shared__ float Bs[BKK][BN];
    int t = threadIdx.x;
    const float* Ab = A + (size_t)(blockIdx.y * BM) * K;
    const float* Bb = Bm + blockIdx.x * BN;
    int aRow = t >> 2, aCol = (t & 3) << 2;
    int bRow = t >> 5, bCol = (t & 31) << 2;
    int tr = (t >> 4) << 3, tc = (t & 15) << 3;

    float acc[8][8];
    #pragma unroll
    for (int i = 0; i < 8; i++)
        #pragma unroll
        for (int j = 0; j < 8; j++) acc[i][j] = 0.f;

    for (int k0 = 0; k0 < K; k0 += BKK) {
        #pragma unroll
        for (int i = 0; i < 2; i++) {
            int r = aRow + i * 64;
            float4 v = *reinterpret_cast<const float4*>(Ab + (size_t)r * K + k0 + aCol);
            As[aCol + 0][r] = v.x;
            As[aCol + 1][r] = v.y;
            As[aCol + 2][r] = v.z;
            As[aCol + 3][r] = v.w;
        }
        #pragma unroll
        for (int i = 0; i < 2; i++) {
            int r = bRow + i * 8;
            *reinterpret_cast<float4*>(&Bs[r][bCol]) =
                *reinterpret_cast<const float4*>(Bb + (size_t)(k0 + r) * N + bCol);
        }
        __syncthreads();
        #pragma unroll
        for (int kk = 0; kk < BKK; kk++) {
            float a[8], bb[8];
            #pragma unroll
            for (int i = 0; i < 8; i++) a[i] = As[kk][tr + i];
            #pragma unroll
            for (int j = 0; j < 8; j++) bb[j] = Bs[kk][tc + j];
            #pragma unroll
            for (int i = 0; i < 8; i++)
                #pragma unroll
                for (int j = 0; j < 8; j++) acc[i][j] += a[i] * bb[j];
        }
        __syncthreads();
    }

    int gy0 = blockIdx.y * BM + tr;
    int gx0 = blockIdx.x * BN + tc;
    #pragma unroll
    for (int i = 0; i < 8; i++) {
        #pragma unroll
        for (int j = 0; j < 8; j += 4) {
            float4 v;
            v.x = acc[i][j];
            v.y = acc[i][j + 1];
            v.z = acc[i][j + 2];
            v.w = acc[i][j + 3];
            if (bias) {
                v.x += bias[gx0 + j];
                v.y += bias[gx0 + j + 1];
                v.z += bias[gx0 + j + 2];
                v.w += bias[gx0 + j + 3];
            }
            *reinterpret_cast<float4*>(C + (size_t)(gy0 + i) * N + gx0 + j) = v;
        }
    }
}

// ============================================================
// 4) flash attention fp32, 64x64 tiles, causal + ALiBi(+j*slope)
//    writes O straight into g_xo columns [0,512)
// ============================================================
#define ATTN_SMEM (4 * 64 * 68 * 4)
__global__ __launch_bounds__(256) void attn_kernel(const float* __restrict__ proj,
                                                   float* __restrict__ xo)
{
    extern __shared__ float sm[];
    float (*Qs)[68] = reinterpret_cast<float(*)[68]>(sm);
    float (*Kt)[68] = reinterpret_cast<float(*)[68]>(sm + 64 * 68);      // [d][j]
    float (*Vs)[68] = reinterpret_cast<float(*)[68]>(sm + 2 * 64 * 68);  // [j][d]
    float (*Ss)[68] = reinterpret_cast<float(*)[68]>(sm + 3 * 64 * 68);  // [r][j]

    int qt = blockIdx.x;          // 0..31
    int bh = blockIdx.y;          // 0..15
    int b = bh >> 3, h = bh & 7;
    int q0 = qt * 64;
    int t = threadIdx.x;
    int r0 = (t >> 4) << 2;       // 4 rows per thread
    int c0 = (t & 15) << 2;       // 4 cols per thread

    const float* projb = proj + (size_t)b * LL * QKVP;

    // load Q tile (64 x 64)
    {
        int r = t >> 2, dbase = (t & 3) << 4;
        const float* qp = projb + (size_t)(q0 + r) * QKVP + h * 64 + dbase;
        #pragma unroll
        for (int i = 0; i < 4; i++)
            *reinterpret_cast<float4*>(&Qs[r][dbase + 4 * i]) =
                *reinterpret_cast<const float4*>(qp + 4 * i);
    }

    float Oacc[4][4];
    float m_run[4], l_run[4];
    #pragma unroll
    for (int i = 0; i < 4; i++) {
        m_run[i] = -1e30f;
        l_run[i] = 0.f;
        #pragma unroll
        for (int j = 0; j < 4; j++) Oacc[i][j] = 0.f;
    }
    float slope = exp2f(-(float)(h + 1));

    int jld = t >> 2, dld = (t & 3) << 4;
    const float* kbase = projb + (size_t)jld * QKVP + HID + h * 64 + dld;
    const float* vbase = projb + (size_t)jld * QKVP + 2 * HID + h * 64 + dld;

    for (int kt = 0; kt <= qt; kt++) {
        int k0 = kt * 64;
        __syncthreads();
        // load K (transposed) and V tiles
        {
            const float* kp = kbase + (size_t)k0 * QKVP;
            float4 a = *reinterpret_cast<const float4*>(kp);
            float4 bq = *reinterpret_cast<const float4*>(kp + 4);
            float4 cq = *reinterpret_cast<const float4*>(kp + 8);
            float4 dq = *reinterpret_cast<const float4*>(kp + 12);
            Kt[dld + 0][jld] = a.x;  Kt[dld + 1][jld] = a.y;
            Kt[dld + 2][jld] = a.z;  Kt[dld + 3][jld] = a.w;
            Kt[dld + 4][jld] = bq.x; Kt[dld + 5][jld] = bq.y;
            Kt[dld + 6][jld] = bq.z; Kt[dld + 7][jld] = bq.w;
            Kt[dld + 8][jld] = cq.x; Kt[dld + 9][jld] = cq.y;
            Kt[dld + 10][jld] = cq.z; Kt[dld + 11][jld] = cq.w;
            Kt[dld + 12][jld] = dq.x; Kt[dld + 13][jld] = dq.y;
            Kt[dld + 14][jld] = dq.z; Kt[dld + 15][jld] = dq.w;
            const float* vp = vbase + (size_t)k0 * QKVP;
            #pragma unroll
            for (int i = 0; i < 4; i++)
                *reinterpret_cast<float4*>(&Vs[jld][dld + 4 * i]) =
                    *reinterpret_cast<const float4*>(vp + 4 * i);
        }
        __syncthreads();

        // S = Q K^T (4x4 microtile)
        float s[4][4];
        #pragma unroll
        for (int i = 0; i < 4; i++)
            #pragma unroll
            for (int j = 0; j < 4; j++) s[i][j] = 0.f;
        #pragma unroll
        for (int d = 0; d < 64; d++) {
            float4 kv = *reinterpret_cast<const float4*>(&Kt[d][c0]);
            float qv[4];
            #pragma unroll
            for (int i = 0; i < 4; i++) qv[i] = Qs[r0 + i][d];
            #pragma unroll
            for (int i = 0; i < 4; i++) {
                s[i][0] += qv[i] * kv.x;
                s[i][1] += qv[i] * kv.y;
                s[i][2] += qv[i] * kv.z;
                s[i][3] += qv[i] * kv.w;
            }
        }

        // scale + alibi + causal mask (only diagonal tile can violate)
        bool diag = (kt == qt);
        float mloc[4];
        #pragma unroll
        for (int i = 0; i < 4; i++) {
            int ig = q0 + r0 + i;
            float mm = -1e30f;
            #pragma unroll
            for (int j = 0; j < 4; j++) {
                int jg = k0 + c0 + j;
                float v = s[i][j] * 0.125f + slope * (float)jg;
                if (diag && jg > ig) v = -1e30f;
                s[i][j] = v;
                mm = fmaxf(mm, v);
            }
            mloc[i] = mm;
        }
        #pragma unroll
        for (int o = 1; o < 16; o <<= 1)
            #pragma unroll
            for (int i = 0; i < 4; i++)
                mloc[i] = fmaxf(mloc[i], __shfl_xor_sync(0xffffffffu, mloc[i], o));

        float lloc[4];
        #pragma unroll
        for (int i = 0; i < 4; i++) {
            float mnew = fmaxf(m_run[i], mloc[i]);
            float sc = __expf(m_run[i] - mnew);
            m_run[i] = mnew;
            float la = 0.f;
            #pragma unroll
            for (int j = 0; j < 4; j++) {
                float p = __expf(s[i][j] - mnew);
                s[i][j] = p;
                la += p;
            }
            lloc[i] = la;
            l_run[i] *= sc;
            #pragma unroll
            for (int j = 0; j < 4; j++) Oacc[i][j] *= sc;
        }
        #pragma unroll
        for (int o = 1; o < 16; o <<= 1)
            #pragma unroll
            for (int i = 0; i < 4; i++)
                lloc[i] += __shfl_xor_sync(0xffffffffu, lloc[i], o);
        #pragma unroll
        for (int i = 0; i < 4; i++) l_run[i] += lloc[i];

        // publish P
        #pragma unroll
        for (int i = 0; i < 4; i++)
            #pragma unroll
            for (int j = 0; j < 4; j++) Ss[r0 + i][c0 + j] = s[i][j];
        __syncthreads();

        // O += P V
        #pragma unroll
        for (int j = 0; j < 64; j++) {
            float4 vv = *reinterpret_cast<const float4*>(&Vs[j][c0]);
            float pv[4];
            #pragma unroll
            for (int i = 0; i < 4; i++) pv[i] = Ss[r0 + i][j];
            #pragma unroll
            for (int i = 0; i < 4; i++) {
                Oacc[i][0] += pv[i] * vv.x;
                Oacc[i][1] += pv[i] * vv.y;
                Oacc[i][2] += pv[i] * vv.z;
                Oacc[i][3] += pv[i] * vv.w;
            }
        }
    }

    #pragma unroll
    for (int i = 0; i < 4; i++) {
        float inv = 1.f / l_run[i];
        float4 v;
        v.x = Oacc[i][0] * inv;
        v.y = Oacc[i][1] * inv;
        v.z = Oacc[i][2] * inv;
        v.w = Oacc[i][3] * inv;
        *reinterpret_cast<float4*>(xo + (size_t)(b * LL + q0 + r0 + i) * VP + h * 64 + c0) = v;
    }
}

// ============================================================
// 5) exact GELU of p into g_xo columns [512, 2560)
// ============================================================
__global__ __launch_bounds__(256) void gelu_kernel()
{
    int idx = blockIdx.x * blockDim.x + threadIdx.x;
    const int total = TOK * 2048 / 4;
    for (int i = idx; i < total; i += gridDim.x * blockDim.x) {
        int tok = i >> 9;          // 512 float4 per token
        int e4 = i & 511;
        float4 v = *reinterpret_cast<const float4*>(g_proj + (size_t)tok * QKVP + 1536 + 4 * e4);
        v.x = v.x * normcdff(v.x);
        v.y = v.y * normcdff(v.y);
        v.z = v.z * normcdff(v.z);
        v.w = v.w * normcdff(v.w);
        *reinterpret_cast<float4*>(g_xo + (size_t)tok * VP + 512 + 4 * e4) = v;
    }
}

// ============================================================
// launch
// ============================================================
extern "C" void kernel_launch(void* const* d_in, const int* in_sizes, int n_in,
                              void* d_out, int out_size)
{
    const float* x     = (const float*)d_in[0];
    const float* gamma = (const float*)d_in[1];
    const float* beta  = (const float*)d_in[2];
    const float* w_in  = (const float*)d_in[3];
    const float* w_out = (const float*)d_in[4];
    const float* b_out = (const float*)d_in[5];
    float* out = (float*)d_out;

    float *xt, *proj, *xo;
    cudaGetSymbolAddress((void**)&xt, g_xt);
    cudaGetSymbolAddress((void**)&proj, g_proj);
    cudaGetSymbolAddress((void**)&xo, g_xo);

    cudaFuncSetAttribute(attn_kernel, cudaFuncAttributeMaxDynamicSharedMemorySize, ATTN_SMEM);

    ln_kernel<<<TOK, 128>>>(x, gamma, beta);
    scan_kernel<<<32, 128>>>();
    sgemm<<<dim3(QKVP / 128, TOK / 128), 256>>>(xt, w_in, nullptr, proj, TOK, QKVP, HID);
    attn_kernel<<<dim3(LL / 64, BB * HH), 256, ATTN_SMEM>>>(proj, xo);
    gelu_kernel<<<2048, 256>>>();
    sgemm<<<dim3(HID / 128, TOK / 128), 256>>>(xo, w_out, b_out, out, TOK, HID, VP);
}

// round 3
// speedup vs baseline: 1.7422x; 1.7422x over previous
#include <cuda_runtime.h>
#include <cuda_bf16.h>
#include <math.h>
#include <stdint.h>

#define BB 2
#define LL 2048
#define HH 8
#define DH 64
#define HID 512
#define QKVP 3584
#define VP 2560
#define TOK (BB*LL)

// ---- static scratch (no allocations allowed) ----
__device__ float g_xt[TOK * HID];                       // fp32 transformed features
__device__ float g_scan[BB * 64 * LL];                  // scan channels [b][c][l]
__device__ float g_proj[(size_t)TOK * QKVP];            // q|k|v|p fp32
__device__ __nv_bfloat16 g_A1h[(size_t)TOK * HID];
__device__ __nv_bfloat16 g_A1l[(size_t)TOK * HID];
__device__ __nv_bfloat16 g_B1h[(size_t)QKVP * HID];     // w_in^T  [N][K]
__device__ __nv_bfloat16 g_B1l[(size_t)QKVP * HID];
__device__ __nv_bfloat16 g_A2h[(size_t)TOK * VP];
__device__ __nv_bfloat16 g_A2l[(size_t)TOK * VP];
__device__ __nv_bfloat16 g_B2h[(size_t)HID * VP];       // w_out^T [N][K]
__device__ __nv_bfloat16 g_B2l[(size_t)HID * VP];

// ============================================================
// helpers
// ============================================================
__device__ __forceinline__ uint32_t smem_u32(const void* p) {
    uint32_t a;
    asm("{ .reg .u64 t; cvta.to.shared.u64 t, %1; cvt.u32.u64 %0, t; }" : "=r"(a) : "l"(p));
    return a;
}
__device__ __forceinline__ void ldsm_x4(uint32_t addr, uint32_t* r) {
    asm volatile("ldmatrix.sync.aligned.m8n8.x4.shared.b16 {%0,%1,%2,%3}, [%4];"
                 : "=r"(r[0]), "=r"(r[1]), "=r"(r[2]), "=r"(r[3]) : "r"(addr));
}
__device__ __forceinline__ void mma_bf16(float* c, const uint32_t* a, uint32_t b0, uint32_t b1) {
    asm volatile("mma.sync.aligned.m16n8k16.row.col.f32.bf16.bf16.f32 "
                 "{%0,%1,%2,%3}, {%4,%5,%6,%7}, {%8,%9}, {%0,%1,%2,%3};"
                 : "+f"(c[0]), "+f"(c[1]), "+f"(c[2]), "+f"(c[3])
                 : "r"(a[0]), "r"(a[1]), "r"(a[2]), "r"(a[3]), "r"(b0), "r"(b1));
}

// ============================================================
// 1) LayerNorm + feature scatter
// ============================================================
__global__ __launch_bounds__(128) void ln_kernel(const float* __restrict__ x,
                                                 const float* __restrict__ gamma,
                                                 const float* __restrict__ beta)
{
    int tok = blockIdx.x;
    int b = tok / LL, l = tok % LL;
    int t = threadIdx.x;

    float4 v = reinterpret_cast<const float4*>(x + (size_t)tok * HID)[t];
    float s  = v.x + v.y + v.z + v.w;
    float s2 = v.x*v.x + v.y*v.y + v.z*v.z + v.w*v.w;
    #pragma unroll
    for (int o = 16; o; o >>= 1) {
        s  += __shfl_xor_sync(0xffffffffu, s,  o);
        s2 += __shfl_xor_sync(0xffffffffu, s2, o);
    }
    __shared__ float red[8];
    __shared__ float stats[2];
    int w = t >> 5;
    if ((t & 31) == 0) { red[w] = s; red[4 + w] = s2; }
    __syncthreads();
    if (t == 0) {
        float ts  = red[0] + red[1] + red[2] + red[3];
        float ts2 = red[4] + red[5] + red[6] + red[7];
        float mu  = ts * (1.f / HID);
        float var = ts2 * (1.f / HID) - mu * mu;
        stats[0] = mu;
        stats[1] = rsqrtf(var + 1e-5f);
    }
    __syncthreads();
    float mu = stats[0], rstd = stats[1];

    float4 g  = reinterpret_cast<const float4*>(gamma)[t];
    float4 be = reinterpret_cast<const float4*>(beta)[t];
    float4 xn;
    xn.x = (v.x - mu) * rstd * g.x + be.x;
    xn.y = (v.y - mu) * rstd * g.y + be.y;
    xn.z = (v.z - mu) * rstd * g.z + be.z;
    xn.w = (v.w - mu) * rstd * g.w + be.w;

    int c0 = t * 4;
    if (c0 < 320) {
        *reinterpret_cast<float4*>(g_xt + (size_t)tok * HID + c0) = xn;
    } else if (c0 < 384) {
        int cc = c0 - 320;
        g_scan[((size_t)b * 64 + cc + 0) * LL + l] = xn.x;
        g_scan[((size_t)b * 64 + cc + 1) * LL + l] = xn.y;
        g_scan[((size_t)b * 64 + cc + 2) * LL + l] = xn.z;
        g_scan[((size_t)b * 64 + cc + 3) * LL + l] = xn.w;
    } else if (c0 < 448) {
        if (l + 1 < LL)
            *reinterpret_cast<float4*>(g_xt + (size_t)(tok + 1) * HID + c0) = xn;
        if (l == 0) {
            float4 z = make_float4(0.f, 0.f, 0.f, 0.f);
            *reinterpret_cast<float4*>(g_xt + (size_t)tok * HID + c0) = z;
        }
    } else {
        if (l + 2 < LL)
            *reinterpret_cast<float4*>(g_xt + (size_t)(tok + 2) * HID + c0) = xn;
        if (l == 0) {
            float4 z = make_float4(0.f, 0.f, 0.f, 0.f);
            *reinterpret_cast<float4*>(g_xt + (size_t)tok * HID + c0) = z;
            *reinterpret_cast<float4*>(g_xt + (size_t)(tok + 1) * HID + c0) = z;
        }
    }
}

// ============================================================
// 2) cumlogsumexp scan
// ============================================================
__global__ __launch_bounds__(128) void scan_kernel()
{
    int wglob = blockIdx.x * 4 + (threadIdx.x >> 5);
    int lane  = threadIdx.x & 31;
    int b = wglob >> 6, c = wglob & 63;
    const float* src = g_scan + ((size_t)b * 64 + c) * LL;

    float M = -1e30f;
    for (int i = lane; i < LL; i += 32) M = fmaxf(M, src[i] * 5.f);
    #pragma unroll
    for (int o = 16; o; o >>= 1) M = fmaxf(M, __shfl_xor_sync(0xffffffffu, M, o));

    float carry = 0.f;
    float* dst = g_xt + 320 + c;
    for (int i0 = 0; i0 < LL; i0 += 32) {
        float e = expf(src[i0 + lane] * 5.f - M);
        float sc = e;
        #pragma unroll
        for (int o = 1; o < 32; o <<= 1) {
            float n = __shfl_up_sync(0xffffffffu, sc, o);
            if (lane >= o) sc += n;
        }
        float val = (M + logf(carry + sc)) * 0.2f;
        dst[(size_t)(b * LL + i0 + lane) * HID] = val;
        carry += __shfl_sync(0xffffffffu, sc, 31);
    }
}

// ============================================================
// 3a) fp32 -> (hi, lo) bf16 split
// ============================================================
__global__ __launch_bounds__(256) void cvt_kernel(const float* __restrict__ src,
                                                  __nv_bfloat16* __restrict__ hi,
                                                  __nv_bfloat16* __restrict__ lo,
                                                  int n4)
{
    int i = blockIdx.x * blockDim.x + threadIdx.x;
    if (i >= n4) return;
    float4 v = reinterpret_cast<const float4*>(src)[i];
    __nv_bfloat162 h0 = __floats2bfloat162_rn(v.x, v.y);
    __nv_bfloat162 h1 = __floats2bfloat162_rn(v.z, v.w);
    __nv_bfloat162 l0 = __floats2bfloat162_rn(v.x - __low2float(h0), v.y - __high2float(h0));
    __nv_bfloat162 l1 = __floats2bfloat162_rn(v.z - __low2float(h1), v.w - __high2float(h1));
    reinterpret_cast<__nv_bfloat162*>(hi)[2 * i]     = h0;
    reinterpret_cast<__nv_bfloat162*>(hi)[2 * i + 1] = h1;
    reinterpret_cast<__nv_bfloat162*>(lo)[2 * i]     = l0;
    reinterpret_cast<__nv_bfloat162*>(lo)[2 * i + 1] = l1;
}

// ============================================================
// 3b) transpose + split: W[K][N] fp32 -> T[N][K] hi/lo bf16
// ============================================================
__global__ __launch_bounds__(256) void transcvt_kernel(const float* __restrict__ W,
                                                       __nv_bfloat16* __restrict__ Th,
                                                       __nv_bfloat16* __restrict__ Tl,
                                                       int K, int N)
{
    __shared__ float tile[32][33];
    int n0 = blockIdx.x * 32, k0 = blockIdx.y * 32;
    int tx = threadIdx.x & 31, ty = threadIdx.x >> 5;
    for (int j = ty; j < 32; j += 8)
        tile[j][tx] = W[(size_t)(k0 + j) * N + n0 + tx];
    __syncthreads();
    for (int j = ty; j < 32; j += 8) {
        float v = tile[tx][j];
        __nv_bfloat16 h = __float2bfloat16(v);
        __nv_bfloat16 l = __float2bfloat16(v - __bfloat162float(h));
        Th[(size_t)(n0 + j) * K + k0 + tx] = h;
        Tl[(size_t)(n0 + j) * K + k0 + tx] = l;
    }
}

// ============================================================
// 4) HMMA bf16x3 GEMM: C[M,N] = A @ B^T (+bias)
//    A:[M][K] hi/lo, B:[N][K] hi/lo. CTA tile 128x128, 8 warps of 64x32.
//    K-chunk 32, double-buffered smem, rows padded to 40 bf16.
// ============================================================
#define PADR 40
#define MATB (128 * PADR * 2)          // 10240 bytes per matrix
#define BUFB (4 * MATB)                // Ah, Al, Bh, Bl
#define GEMM_SMEM (2 * BUFB)           // 81920 bytes

__global__ __launch_bounds__(256) void gemm_tc(const __nv_bfloat16* __restrict__ Ah,
                                               const __nv_bfloat16* __restrict__ Al,
                                               const __nv_bfloat16* __restrict__ Bh,
                                               const __nv_bfloat16* __restrict__ Bl,
                                               const float* __restrict__ bias,
                                               float* __restrict__ C,
                                               int M, int N, int K)
{
    extern __shared__ char sm[];
    uint32_t sb = smem_u32(sm);
    int t = threadIdx.x, lane = t & 31, wid = t >> 5;
    int wm = wid >> 2, wc = wid & 3;                 // warp grid 2 x 4
    int m0 = blockIdx.y * 128, n0 = blockIdx.x * 128;

    // ldmatrix lane offsets (byte offsets within a matrix)
    uint32_t aoff[4], boff[2];
    #pragma unroll
    for (int i = 0; i < 4; i++)
        aoff[i] = ((wm * 64 + i * 16 + (lane & 15)) * PADR + (lane >> 4) * 8) * 2;
    #pragma unroll
    for (int jj = 0; jj < 2; jj++)
        boff[jj] = ((wc * 32 + (2 * jj + (lane >> 4)) * 8 + (lane & 7)) * PADR
                    + ((lane >> 3) & 1) * 8) * 2;

    // global load mapping: each thread owns (row = t>>1, 16 cols at half*16)
    int grow = t >> 1, ghalf = (t & 1) * 16;
    const __nv_bfloat16* pAh = Ah + (size_t)(m0 + grow) * K + ghalf;
    const __nv_bfloat16* pAl = Al + (size_t)(m0 + grow) * K + ghalf;
    const __nv_bfloat16* pBh = Bh + (size_t)(n0 + grow) * K + ghalf;
    const __nv_bfloat16* pBl = Bl + (size_t)(n0 + grow) * K + ghalf;
    uint32_t so0 = (grow * PADR + ghalf) * 2;        // byte offset in matrix
    uint32_t so1 = so0 + 16;

    float acc[4][4][4];
    #pragma unroll
    for (int i = 0; i < 4; i++)
        #pragma unroll
        for (int j = 0; j < 4; j++)
            #pragma unroll
            for (int q = 0; q < 4; q++) acc[i][j][q] = 0.f;

    const int nC = K / 32;

    // preload chunk 0 into buffer 0
    {
        char* b = sm;
        *reinterpret_cast<uint4*>(b + so0)            = *reinterpret_cast<const uint4*>(pAh);
        *reinterpret_cast<uint4*>(b + so1)            = *reinterpret_cast<const uint4*>(pAh + 8);
        *reinterpret_cast<uint4*>(b + MATB + so0)     = *reinterpret_cast<const uint4*>(pAl);
        *reinterpret_cast<uint4*>(b + MATB + so1)     = *reinterpret_cast<const uint4*>(pAl + 8);
        *reinterpret_cast<uint4*>(b + 2*MATB + so0)   = *reinterpret_cast<const uint4*>(pBh);
        *reinterpret_cast<uint4*>(b + 2*MATB + so1)   = *reinterpret_cast<const uint4*>(pBh + 8);
        *reinterpret_cast<uint4*>(b + 3*MATB + so0)   = *reinterpret_cast<const uint4*>(pBl);
        *reinterpret_cast<uint4*>(b + 3*MATB + so1)   = *reinterpret_cast<const uint4*>(pBl + 8);
    }
    __syncthreads();

    for (int c = 0; c < nC; c++) {
        uint4 f0, f1, f2, f3, f4, f5, f6, f7;
        if (c + 1 < nC) {
            int ko = (c + 1) * 32;
            f0 = *reinterpret_cast<const uint4*>(pAh + ko);
            f1 = *reinterpret_cast<const uint4*>(pAh + ko + 8);
            f2 = *reinterpret_cast<const uint4*>(pAl + ko);
            f3 = *reinterpret_cast<const uint4*>(pAl + ko + 8);
            f4 = *reinterpret_cast<const uint4*>(pBh + ko);
            f5 = *reinterpret_cast<const uint4*>(pBh + ko + 8);
            f6 = *reinterpret_cast<const uint4*>(pBl + ko);
            f7 = *reinterpret_cast<const uint4*>(pBl + ko + 8);
        }

        uint32_t base = sb + (c & 1) * BUFB;
        #pragma unroll
        for (int ks = 0; ks < 2; ks++) {
            uint32_t ah[4][4], alr[4][4], bh[2][4], bl[2][4];
            #pragma unroll
            for (int i = 0; i < 4; i++) ldsm_x4(base + aoff[i] + ks * 32, ah[i]);
            #pragma unroll
            for (int i = 0; i < 4; i++) ldsm_x4(base + MATB + aoff[i] + ks * 32, alr[i]);
            #pragma unroll
            for (int jj = 0; jj < 2; jj++) ldsm_x4(base + 2*MATB + boff[jj] + ks * 32, bh[jj]);
            #pragma unroll
            for (int jj = 0; jj < 2; jj++) ldsm_x4(base + 3*MATB + boff[jj] + ks * 32, bl[jj]);

            #pragma unroll
            for (int i = 0; i < 4; i++) {
                #pragma unroll
                for (int j = 0; j < 4; j++) {
                    uint32_t b0h = bh[j >> 1][(j & 1) * 2], b1h = bh[j >> 1][(j & 1) * 2 + 1];
                    uint32_t b0l = bl[j >> 1][(j & 1) * 2], b1l = bl[j >> 1][(j & 1) * 2 + 1];
                    mma_bf16(acc[i][j], ah[i],  b0h, b1h);
                    mma_bf16(acc[i][j], ah[i],  b0l, b1l);
                    mma_bf16(acc[i][j], alr[i], b0h, b1h);
                }
            }
        }

        if (c + 1 < nC) {
            char* b = sm + ((c + 1) & 1) * BUFB;
            *reinterpret_cast<uint4*>(b + so0)          = f0;
            *reinterpret_cast<uint4*>(b + so1)          = f1;
            *reinterpret_cast<uint4*>(b + MATB + so0)   = f2;
            *reinterpret_cast<uint4*>(b + MATB + so1)   = f3;
            *reinterpret_cast<uint4*>(b + 2*MATB + so0) = f4;
            *reinterpret_cast<uint4*>(b + 2*MATB + so1) = f5;
            *reinterpret_cast<uint4*>(b + 3*MATB + so0) = f6;
            *reinterpret_cast<uint4*>(b + 3*MATB + so1) = f7;
            __syncthreads();
        }
    }

    // epilogue
    int r = lane >> 2, cp = (lane & 3) * 2;
    #pragma unroll
    for (int i = 0; i < 4; i++) {
        int gr = m0 + wm * 64 + i * 16 + r;
        #pragma unroll
        for (int j = 0; j < 4; j++) {
            int gc = n0 + wc * 32 + j * 8 + cp;
            float b0 = bias ? bias[gc] : 0.f;
            float b1 = bias ? bias[gc + 1] : 0.f;
            float2 v0 = make_float2(acc[i][j][0] + b0, acc[i][j][1] + b1);
            float2 v1 = make_float2(acc[i][j][2] + b0, acc[i][j][3] + b1);
            *reinterpret_cast<float2*>(C + (size_t)gr * N + gc) = v0;
            *reinterpret_cast<float2*>(C + (size_t)(gr + 8) * N + gc) = v1;
        }
    }
}

// ============================================================
// 5) flash attention fp32 -> hi/lo bf16 into A2 cols [0,512)
// ============================================================
#define ATTN_SMEM (4 * 64 * 68 * 4)
__global__ __launch_bounds__(256) void attn_kernel(const float* __restrict__ proj,
                                                   __nv_bfloat16* __restrict__ oh,
                                                   __nv_bfloat16* __restrict__ ol)
{
    extern __shared__ float smf[];
    float (*Qs)[68] = reinterpret_cast<float(*)[68]>(smf);
    float (*Kt)[68] = reinterpret_cast<float(*)[68]>(smf + 64 * 68);
    float (*Vs)[68] = reinterpret_cast<float(*)[68]>(smf + 2 * 64 * 68);
    float (*Ss)[68] = reinterpret_cast<float(*)[68]>(smf + 3 * 64 * 68);

    int qt = gridDim.x - 1 - blockIdx.x;
    int bh = blockIdx.y;
    int b = bh >> 3, hd = bh & 7;
    int q0 = qt * 64;
    int t = threadIdx.x;
    int r0 = (t >> 4) << 2;
    int c0 = (t & 15) << 2;

    const float* projb = proj + (size_t)b * LL * QKVP;

    {
        int r = t >> 2, dbase = (t & 3) << 4;
        const float* qp = projb + (size_t)(q0 + r) * QKVP + hd * 64 + dbase;
        #pragma unroll
        for (int i = 0; i < 4; i++)
            *reinterpret_cast<float4*>(&Qs[r][dbase + 4 * i]) =
                *reinterpret_cast<const float4*>(qp + 4 * i);
    }

    float Oacc[4][4];
    float m_run[4], l_run[4];
    #pragma unroll
    for (int i = 0; i < 4; i++) {
        m_run[i] = -1e30f;
        l_run[i] = 0.f;
        #pragma unroll
        for (int j = 0; j < 4; j++) Oacc[i][j] = 0.f;
    }
    float slope = exp2f(-(float)(hd + 1));

    int jld = t >> 2, dld = (t & 3) << 4;
    const float* kbase = projb + (size_t)jld * QKVP + HID + hd * 64 + dld;
    const float* vbase = projb + (size_t)jld * QKVP + 2 * HID + hd * 64 + dld;

    for (int kt = 0; kt <= qt; kt++) {
        int k0 = kt * 64;
        __syncthreads();
        {
            const float* kp = kbase + (size_t)k0 * QKVP;
            float4 a = *reinterpret_cast<const float4*>(kp);
            float4 bq = *reinterpret_cast<const float4*>(kp + 4);
            float4 cq = *reinterpret_cast<const float4*>(kp + 8);
            float4 dq = *reinterpret_cast<const float4*>(kp + 12);
            Kt[dld + 0][jld] = a.x;  Kt[dld + 1][jld] = a.y;
            Kt[dld + 2][jld] = a.z;  Kt[dld + 3][jld] = a.w;
            Kt[dld + 4][jld] = bq.x; Kt[dld + 5][jld] = bq.y;
            Kt[dld + 6][jld] = bq.z; Kt[dld + 7][jld] = bq.w;
            Kt[dld + 8][jld] = cq.x; Kt[dld + 9][jld] = cq.y;
            Kt[dld + 10][jld] = cq.z; Kt[dld + 11][jld] = cq.w;
            Kt[dld + 12][jld] = dq.x; Kt[dld + 13][jld] = dq.y;
            Kt[dld + 14][jld] = dq.z; Kt[dld + 15][jld] = dq.w;
            const float* vp = vbase + (size_t)k0 * QKVP;
            #pragma unroll
            for (int i = 0; i < 4; i++)
                *reinterpret_cast<float4*>(&Vs[jld][dld + 4 * i]) =
                    *reinterpret_cast<const float4*>(vp + 4 * i);
        }
        __syncthreads();

        float s[4][4];
        #pragma unroll
        for (int i = 0; i < 4; i++)
            #pragma unroll
            for (int j = 0; j < 4; j++) s[i][j] = 0.f;
        #pragma unroll
        for (int d = 0; d < 64; d++) {
            float4 kv = *reinterpret_cast<const float4*>(&Kt[d][c0]);
            float qv[4];
            #pragma unroll
            for (int i = 0; i < 4; i++) qv[i] = Qs[r0 + i][d];
            #pragma unroll
            for (int i = 0; i < 4; i++) {
                s[i][0] += qv[i] * kv.x;
                s[i][1] += qv[i] * kv.y;
                s[i][2] += qv[i] * kv.z;
                s[i][3] += qv[i] * kv.w;
            }
        }

        bool diag = (kt == qt);
        float mloc[4];
        #pragma unroll
        for (int i = 0; i < 4; i++) {
            int ig = q0 + r0 + i;
            float mm = -1e30f;
            #pragma unroll
            for (int j = 0; j < 4; j++) {
                int jg = k0 + c0 + j;
                float v = s[i][j] * 0.125f + slope * (float)jg;
                if (diag && jg > ig) v = -1e30f;
                s[i][j] = v;
                mm = fmaxf(mm, v);
            }
            mloc[i] = mm;
        }
        #pragma unroll
        for (int o = 1; o < 16; o <<= 1)
            #pragma unroll
            for (int i = 0; i < 4; i++)
                mloc[i] = fmaxf(mloc[i], __shfl_xor_sync(0xffffffffu, mloc[i], o));

        float lloc[4];
        #pragma unroll
        for (int i = 0; i < 4; i++) {
            float mnew = fmaxf(m_run[i], mloc[i]);
            float sc = __expf(m_run[i] - mnew);
            m_run[i] = mnew;
            float la = 0.f;
            #pragma unroll
            for (int j = 0; j < 4; j++) {
                float p = __expf(s[i][j] - mnew);
                s[i][j] = p;
                la += p;
            }
            lloc[i] = la;
            l_run[i] *= sc;
            #pragma unroll
            for (int j = 0; j < 4; j++) Oacc[i][j] *= sc;
        }
        #pragma unroll
        for (int o = 1; o < 16; o <<= 1)
            #pragma unroll
            for (int i = 0; i < 4; i++)
                lloc[i] += __shfl_xor_sync(0xffffffffu, lloc[i], o);
        #pragma unroll
        for (int i = 0; i < 4; i++) l_run[i] += lloc[i];

        #pragma unroll
        for (int i = 0; i < 4; i++)
            #pragma unroll
            for (int j = 0; j < 4; j++) Ss[r0 + i][c0 + j] = s[i][j];
        __syncthreads();

        #pragma unroll
        for (int j = 0; j < 64; j++) {
            float4 vv = *reinterpret_cast<const float4*>(&Vs[j][c0]);
            float pv[4];
            #pragma unroll
            for (int i = 0; i < 4; i++) pv[i] = Ss[r0 + i][j];
            #pragma unroll
            for (int i = 0; i < 4; i++) {
                Oacc[i][0] += pv[i] * vv.x;
                Oacc[i][1] += pv[i] * vv.y;
                Oacc[i][2] += pv[i] * vv.z;
                Oacc[i][3] += pv[i] * vv.w;
            }
        }
    }

    #pragma unroll
    for (int i = 0; i < 4; i++) {
        float inv = 1.f / l_run[i];
        size_t base = (size_t)(b * LL + q0 + r0 + i) * VP + hd * 64 + c0;
        #pragma unroll
        for (int j = 0; j < 4; j++) {
            float v = Oacc[i][j] * inv;
            __nv_bfloat16 hh = __float2bfloat16(v);
            __nv_bfloat16 llv = __float2bfloat16(v - __bfloat162float(hh));
            oh[base + j] = hh;
            ol[base + j] = llv;
        }
    }
}

// ============================================================
// 6) exact GELU -> hi/lo bf16 into A2 cols [512, 2560)
// ============================================================
__global__ __launch_bounds__(256) void gelu_kernel()
{
    int idx = blockIdx.x * blockDim.x + threadIdx.x;
    const int total = TOK * 2048 / 4;
    for (int i = idx; i < total; i += gridDim.x * blockDim.x) {
        int tok = i >> 9;
        int e4 = i & 511;
        float4 v = *reinterpret_cast<const float4*>(g_proj + (size_t)tok * QKVP + 1536 + 4 * e4);
        v.x = v.x * normcdff(v.x);
        v.y = v.y * normcdff(v.y);
        v.z = v.z * normcdff(v.z);
        v.w = v.w * normcdff(v.w);
        __nv_bfloat162 h0 = __floats2bfloat162_rn(v.x, v.y);
        __nv_bfloat162 h1 = __floats2bfloat162_rn(v.z, v.w);
        __nv_bfloat162 l0 = __floats2bfloat162_rn(v.x - __low2float(h0), v.y - __high2float(h0));
        __nv_bfloat162 l1 = __floats2bfloat162_rn(v.z - __low2float(h1), v.w - __high2float(h1));
        size_t base = (size_t)tok * VP + 512 + 4 * e4;
        *reinterpret_cast<__nv_bfloat162*>(g_A2h + base)     = h0;
        *reinterpret_cast<__nv_bfloat162*>(g_A2h + base + 2) = h1;
        *reinterpret_cast<__nv_bfloat162*>(g_A2l + base)     = l0;
        *reinterpret_cast<__nv_bfloat162*>(g_A2l + base + 2) = l1;
    }
}

// ============================================================
// launch
// ============================================================
extern "C" void kernel_launch(void* const* d_in, const int* in_sizes, int n_in,
                              void* d_out, int out_size)
{
    const float* x     = (const float*)d_in[0];
    const float* gamma = (const float*)d_in[1];
    const float* beta  = (const float*)d_in[2];
    const float* w_in  = (const float*)d_in[3];
    const float* w_out = (const float*)d_in[4];
    const float* b_out = (const float*)d_in[5];
    float* out = (float*)d_out;

    float *xt, *proj;
    __nv_bfloat16 *a1h, *a1l, *b1h, *b1l, *a2h, *a2l, *b2h, *b2l;
    cudaGetSymbolAddress((void**)&xt,   g_xt);
    cudaGetSymbolAddress((void**)&proj, g_proj);
    cudaGetSymbolAddress((void**)&a1h,  g_A1h);
    cudaGetSymbolAddress((void**)&a1l,  g_A1l);
    cudaGetSymbolAddress((void**)&b1h,  g_B1h);
    cudaGetSymbolAddress((void**)&b1l,  g_B1l);
    cudaGetSymbolAddress((void**)&a2h,  g_A2h);
    cudaGetSymbolAddress((void**)&a2l,  g_A2l);
    cudaGetSymbolAddress((void**)&b2h,  g_B2h);
    cudaGetSymbolAddress((void**)&b2l,  g_B2l);

    cudaFuncSetAttribute(attn_kernel, cudaFuncAttributeMaxDynamicSharedMemorySize, ATTN_SMEM);
    cudaFuncSetAttribute(gemm_tc, cudaFuncAttributeMaxDynamicSharedMemorySize, GEMM_SMEM);

    // weight prep (independent of activations)
    transcvt_kernel<<<dim3(QKVP / 32, HID / 32), 256>>>(w_in, b1h, b1l, HID, QKVP);
    transcvt_kernel<<<dim3(HID / 32, VP / 32), 256>>>(w_out, b2h, b2l, VP, HID);

    ln_kernel<<<TOK, 128>>>(x, gamma, beta);
    scan_kernel<<<32, 128>>>();
    cvt_kernel<<<(TOK * HID / 4 + 255) / 256, 256>>>(xt, a1h, a1l, TOK * HID / 4);

    gemm_tc<<<dim3(QKVP / 128, TOK / 128), 256, GEMM_SMEM>>>(
        a1h, a1l, b1h, b1l, nullptr, proj, TOK, QKVP, HID);

    attn_kernel<<<dim3(LL / 64, BB * HH), 256, ATTN_SMEM>>>(proj, a2h, a2l);
    gelu_kernel<<<2048, 256>>>();

    gemm_tc<<<dim3(HID / 128, TOK / 128), 256, GEMM_SMEM>>>(
        a2h, a2l, b2h, b2l, b_out, out, TOK, HID, VP);
}

// round 5
// speedup vs baseline: 2.4998x; 1.4348x over previous
#include <cuda_runtime.h>
#include <cuda_bf16.h>
#include <math.h>
#include <stdint.h>

#define BB 2
#define LL 2048
#define HH 8
#define DH 64
#define HID 512
#define QKVP 3584
#define VP 2560
#define TOK (BB*LL)

// ---- static scratch ----
__device__ float g_xt[TOK * HID];
__device__ float g_scan[BB * 64 * LL];
__device__ float g_proj[(size_t)TOK * QKVP];
__device__ __nv_bfloat16 g_A1h[(size_t)TOK * HID];
__device__ __nv_bfloat16 g_A1l[(size_t)TOK * HID];
__device__ __nv_bfloat16 g_B1h[(size_t)QKVP * HID];
__device__ __nv_bfloat16 g_B1l[(size_t)QKVP * HID];
__device__ __nv_bfloat16 g_A2h[(size_t)TOK * VP];
__device__ __nv_bfloat16 g_A2l[(size_t)TOK * VP];
__device__ __nv_bfloat16 g_B2h[(size_t)HID * VP];
__device__ __nv_bfloat16 g_B2l[(size_t)HID * VP];
// head-major q/k/v hi/lo: [bh][l][64]
#define QKV_ELEMS ((size_t)BB * HH * LL * DH)
__device__ __nv_bfloat16 g_Qh[QKV_ELEMS];
__device__ __nv_bfloat16 g_Ql[QKV_ELEMS];
__device__ __nv_bfloat16 g_Kh[QKV_ELEMS];
__device__ __nv_bfloat16 g_Kl[QKV_ELEMS];
__device__ __nv_bfloat16 g_Vh[QKV_ELEMS];
__device__ __nv_bfloat16 g_Vl[QKV_ELEMS];

// ============================================================
// helpers
// ============================================================
__device__ __forceinline__ uint32_t smem_u32(const void* p) {
    uint32_t a;
    asm("{ .reg .u64 t; cvta.to.shared.u64 t, %1; cvt.u32.u64 %0, t; }" : "=r"(a) : "l"(p));
    return a;
}
__device__ __forceinline__ void ldsm_x4(uint32_t addr, uint32_t* r) {
    asm volatile("ldmatrix.sync.aligned.m8n8.x4.shared.b16 {%0,%1,%2,%3}, [%4];"
                 : "=r"(r[0]), "=r"(r[1]), "=r"(r[2]), "=r"(r[3]) : "r"(addr));
}
__device__ __forceinline__ void ldsm_x4_t(uint32_t addr, uint32_t* r) {
    asm volatile("ldmatrix.sync.aligned.m8n8.x4.trans.shared.b16 {%0,%1,%2,%3}, [%4];"
                 : "=r"(r[0]), "=r"(r[1]), "=r"(r[2]), "=r"(r[3]) : "r"(addr));
}
__device__ __forceinline__ void mma_bf16(float* c, const uint32_t* a, uint32_t b0, uint32_t b1) {
    asm volatile("mma.sync.aligned.m16n8k16.row.col.f32.bf16.bf16.f32 "
                 "{%0,%1,%2,%3}, {%4,%5,%6,%7}, {%8,%9}, {%0,%1,%2,%3};"
                 : "+f"(c[0]), "+f"(c[1]), "+f"(c[2]), "+f"(c[3])
                 : "r"(a[0]), "r"(a[1]), "r"(a[2]), "r"(a[3]), "r"(b0), "r"(b1));
}
__device__ __forceinline__ uint32_t bf2bits(__nv_bfloat162 v) {
    return *reinterpret_cast<uint32_t*>(&v);
}

// ============================================================
// 1) LayerNorm + feature scatter
// ============================================================
__global__ __launch_bounds__(128) void ln_kernel(const float* __restrict__ x,
                                                 const float* __restrict__ gamma,
                                                 const float* __restrict__ beta)
{
    int tok = blockIdx.x;
    int b = tok / LL, l = tok % LL;
    int t = threadIdx.x;

    float4 v = reinterpret_cast<const float4*>(x + (size_t)tok * HID)[t];
    float s  = v.x + v.y + v.z + v.w;
    float s2 = v.x*v.x + v.y*v.y + v.z*v.z + v.w*v.w;
    #pragma unroll
    for (int o = 16; o; o >>= 1) {
        s  += __shfl_xor_sync(0xffffffffu, s,  o);
        s2 += __shfl_xor_sync(0xffffffffu, s2, o);
    }
    __shared__ float red[8];
    __shared__ float stats[2];
    int w = t >> 5;
    if ((t & 31) == 0) { red[w] = s; red[4 + w] = s2; }
    __syncthreads();
    if (t == 0) {
        float ts  = red[0] + red[1] + red[2] + red[3];
        float ts2 = red[4] + red[5] + red[6] + red[7];
        float mu  = ts * (1.f / HID);
        float var = ts2 * (1.f / HID) - mu * mu;
        stats[0] = mu;
        stats[1] = rsqrtf(var + 1e-5f);
    }
    __syncthreads();
    float mu = stats[0], rstd = stats[1];

    float4 g  = reinterpret_cast<const float4*>(gamma)[t];
    float4 be = reinterpret_cast<const float4*>(beta)[t];
    float4 xn;
    xn.x = (v.x - mu) * rstd * g.x + be.x;
    xn.y = (v.y - mu) * rstd * g.y + be.y;
    xn.z = (v.z - mu) * rstd * g.z + be.z;
    xn.w = (v.w - mu) * rstd * g.w + be.w;

    int c0 = t * 4;
    if (c0 < 320) {
        *reinterpret_cast<float4*>(g_xt + (size_t)tok * HID + c0) = xn;
    } else if (c0 < 384) {
        int cc = c0 - 320;
        g_scan[((size_t)b * 64 + cc + 0) * LL + l] = xn.x;
        g_scan[((size_t)b * 64 + cc + 1) * LL + l] = xn.y;
        g_scan[((size_t)b * 64 + cc + 2) * LL + l] = xn.z;
        g_scan[((size_t)b * 64 + cc + 3) * LL + l] = xn.w;
    } else if (c0 < 448) {
        if (l + 1 < LL)
            *reinterpret_cast<float4*>(g_xt + (size_t)(tok + 1) * HID + c0) = xn;
        if (l == 0) {
            float4 z = make_float4(0.f, 0.f, 0.f, 0.f);
            *reinterpret_cast<float4*>(g_xt + (size_t)tok * HID + c0) = z;
        }
    } else {
        if (l + 2 < LL)
            *reinterpret_cast<float4*>(g_xt + (size_t)(tok + 2) * HID + c0) = xn;
        if (l == 0) {
            float4 z = make_float4(0.f, 0.f, 0.f, 0.f);
            *reinterpret_cast<float4*>(g_xt + (size_t)tok * HID + c0) = z;
            *reinterpret_cast<float4*>(g_xt + (size_t)(tok + 1) * HID + c0) = z;
        }
    }
}

// ============================================================
// 2) cumlogsumexp scan
// ============================================================
__global__ __launch_bounds__(128) void scan_kernel()
{
    int wglob = blockIdx.x * 4 + (threadIdx.x >> 5);
    int lane  = threadIdx.x & 31;
    int b = wglob >> 6, c = wglob & 63;
    const float* src = g_scan + ((size_t)b * 64 + c) * LL;

    float M = -1e30f;
    for (int i = lane; i < LL; i += 32) M = fmaxf(M, src[i] * 5.f);
    #pragma unroll
    for (int o = 16; o; o >>= 1) M = fmaxf(M, __shfl_xor_sync(0xffffffffu, M, o));

    float carry = 0.f;
    float* dst = g_xt + 320 + c;
    for (int i0 = 0; i0 < LL; i0 += 32) {
        float e = expf(src[i0 + lane] * 5.f - M);
        float sc = e;
        #pragma unroll
        for (int o = 1; o < 32; o <<= 1) {
            float n = __shfl_up_sync(0xffffffffu, sc, o);
            if (lane >= o) sc += n;
        }
        float val = (M + logf(carry + sc)) * 0.2f;
        dst[(size_t)(b * LL + i0 + lane) * HID] = val;
        carry += __shfl_sync(0xffffffffu, sc, 31);
    }
}

// ============================================================
// 3a) fp32 -> (hi, lo) bf16 split
// ============================================================
__global__ __launch_bounds__(256) void cvt_kernel(const float* __restrict__ src,
                                                  __nv_bfloat16* __restrict__ hi,
                                                  __nv_bfloat16* __restrict__ lo,
                                                  int n4)
{
    int i = blockIdx.x * blockDim.x + threadIdx.x;
    if (i >= n4) return;
    float4 v = reinterpret_cast<const float4*>(src)[i];
    __nv_bfloat162 h0 = __floats2bfloat162_rn(v.x, v.y);
    __nv_bfloat162 h1 = __floats2bfloat162_rn(v.z, v.w);
    __nv_bfloat162 l0 = __floats2bfloat162_rn(v.x - __low2float(h0), v.y - __high2float(h0));
    __nv_bfloat162 l1 = __floats2bfloat162_rn(v.z - __low2float(h1), v.w - __high2float(h1));
    reinterpret_cast<__nv_bfloat162*>(hi)[2 * i]     = h0;
    reinterpret_cast<__nv_bfloat162*>(hi)[2 * i + 1] = h1;
    reinterpret_cast<__nv_bfloat162*>(lo)[2 * i]     = l0;
    reinterpret_cast<__nv_bfloat162*>(lo)[2 * i + 1] = l1;
}

// ============================================================
// 3b) transpose + split: W[K][N] fp32 -> T[N][K] hi/lo bf16
// ============================================================
__global__ __launch_bounds__(256) void transcvt_kernel(const float* __restrict__ W,
                                                       __nv_bfloat16* __restrict__ Th,
                                                       __nv_bfloat16* __restrict__ Tl,
                                                       int K, int N)
{
    __shared__ float tile[32][33];
    int n0 = blockIdx.x * 32, k0 = blockIdx.y * 32;
    int tx = threadIdx.x & 31, ty = threadIdx.x >> 5;
    for (int j = ty; j < 32; j += 8)
        tile[j][tx] = W[(size_t)(k0 + j) * N + n0 + tx];
    __syncthreads();
    for (int j = ty; j < 32; j += 8) {
        float v = tile[tx][j];
        __nv_bfloat16 h = __float2bfloat16(v);
        __nv_bfloat16 l = __float2bfloat16(v - __bfloat162float(h));
        Th[(size_t)(n0 + j) * K + k0 + tx] = h;
        Tl[(size_t)(n0 + j) * K + k0 + tx] = l;
    }
}

// ============================================================
// 3c) qkv head-major hi/lo conversion from proj
// grid: (TOK*HID/4/256, 3)  part 0=q,1=k,2=v
// ============================================================
__global__ __launch_bounds__(256) void qkv_cvt()
{
    int part = blockIdx.y;
    int idx = blockIdx.x * 256 + threadIdx.x;    // quad index within part
    int tok = idx >> 7;
    int rem = idx & 127;
    int h = rem >> 4;
    int d0 = (rem & 15) * 4;

    float4 v = *reinterpret_cast<const float4*>(
        g_proj + (size_t)tok * QKVP + part * HID + h * 64 + d0);
    __nv_bfloat162 h0 = __floats2bfloat162_rn(v.x, v.y);
    __nv_bfloat162 h1 = __floats2bfloat162_rn(v.z, v.w);
    __nv_bfloat162 l0 = __floats2bfloat162_rn(v.x - __low2float(h0), v.y - __high2float(h0));
    __nv_bfloat162 l1 = __floats2bfloat162_rn(v.z - __low2float(h1), v.w - __high2float(h1));

    int bh = (tok >> 11) * 8 + h;
    int l = tok & 2047;
    size_t off = ((size_t)bh * LL + l) * 64 + d0;

    __nv_bfloat16 *dh, *dl;
    if (part == 0)      { dh = g_Qh; dl = g_Ql; }
    else if (part == 1) { dh = g_Kh; dl = g_Kl; }
    else                { dh = g_Vh; dl = g_Vl; }
    *reinterpret_cast<__nv_bfloat162*>(dh + off)     = h0;
    *reinterpret_cast<__nv_bfloat162*>(dh + off + 2) = h1;
    *reinterpret_cast<__nv_bfloat162*>(dl + off)     = l0;
    *reinterpret_cast<__nv_bfloat162*>(dl + off + 2) = l1;
}

// ============================================================
// 4) HMMA bf16x3 GEMM (unchanged from round 3)
// ============================================================
#define PADR 40
#define MATB (128 * PADR * 2)
#define BUFB (4 * MATB)
#define GEMM_SMEM (2 * BUFB)

__global__ __launch_bounds__(256) void gemm_tc(const __nv_bfloat16* __restrict__ Ah,
                                               const __nv_bfloat16* __restrict__ Al,
                                               const __nv_bfloat16* __restrict__ Bh,
                                               const __nv_bfloat16* __restrict__ Bl,
                                               const float* __restrict__ bias,
                                               float* __restrict__ C,
                                               int M, int N, int K)
{
    extern __shared__ char sm[];
    uint32_t sb = smem_u32(sm);
    int t = threadIdx.x, lane = t & 31, wid = t >> 5;
    int wm = wid >> 2, wc = wid & 3;
    int m0 = blockIdx.y * 128, n0 = blockIdx.x * 128;

    uint32_t aoff[4], boff[2];
    #pragma unroll
    for (int i = 0; i < 4; i++)
        aoff[i] = ((wm * 64 + i * 16 + (lane & 15)) * PADR + (lane >> 4) * 8) * 2;
    #pragma unroll
    for (int jj = 0; jj < 2; jj++)
        boff[jj] = ((wc * 32 + (2 * jj + (lane >> 4)) * 8 + (lane & 7)) * PADR
                    + ((lane >> 3) & 1) * 8) * 2;

    int grow = t >> 1, ghalf = (t & 1) * 16;
    const __nv_bfloat16* pAh = Ah + (size_t)(m0 + grow) * K + ghalf;
    const __nv_bfloat16* pAl = Al + (size_t)(m0 + grow) * K + ghalf;
    const __nv_bfloat16* pBh = Bh + (size_t)(n0 + grow) * K + ghalf;
    const __nv_bfloat16* pBl = Bl + (size_t)(n0 + grow) * K + ghalf;
    uint32_t so0 = (grow * PADR + ghalf) * 2;
    uint32_t so1 = so0 + 16;

    float acc[4][4][4];
    #pragma unroll
    for (int i = 0; i < 4; i++)
        #pragma unroll
        for (int j = 0; j < 4; j++)
            #pragma unroll
            for (int q = 0; q < 4; q++) acc[i][j][q] = 0.f;

    const int nC = K / 32;

    {
        char* b = sm;
        *reinterpret_cast<uint4*>(b + so0)            = *reinterpret_cast<const uint4*>(pAh);
        *reinterpret_cast<uint4*>(b + so1)            = *reinterpret_cast<const uint4*>(pAh + 8);
        *reinterpret_cast<uint4*>(b + MATB + so0)     = *reinterpret_cast<const uint4*>(pAl);
        *reinterpret_cast<uint4*>(b + MATB + so1)     = *reinterpret_cast<const uint4*>(pAl + 8);
        *reinterpret_cast<uint4*>(b + 2*MATB + so0)   = *reinterpret_cast<const uint4*>(pBh);
        *reinterpret_cast<uint4*>(b + 2*MATB + so1)   = *reinterpret_cast<const uint4*>(pBh + 8);
        *reinterpret_cast<uint4*>(b + 3*MATB + so0)   = *reinterpret_cast<const uint4*>(pBl);
        *reinterpret_cast<uint4*>(b + 3*MATB + so1)   = *reinterpret_cast<const uint4*>(pBl + 8);
    }
    __syncthreads();

    for (int c = 0; c < nC; c++) {
        uint4 f0, f1, f2, f3, f4, f5, f6, f7;
        if (c + 1 < nC) {
            int ko = (c + 1) * 32;
            f0 = *reinterpret_cast<const uint4*>(pAh + ko);
            f1 = *reinterpret_cast<const uint4*>(pAh + ko + 8);
            f2 = *reinterpret_cast<const uint4*>(pAl + ko);
            f3 = *reinterpret_cast<const uint4*>(pAl + ko + 8);
            f4 = *reinterpret_cast<const uint4*>(pBh + ko);
            f5 = *reinterpret_cast<const uint4*>(pBh + ko + 8);
            f6 = *reinterpret_cast<const uint4*>(pBl + ko);
            f7 = *reinterpret_cast<const uint4*>(pBl + ko + 8);
        }

        uint32_t base = sb + (c & 1) * BUFB;
        #pragma unroll
        for (int ks = 0; ks < 2; ks++) {
            uint32_t ah[4][4], alr[4][4], bh[2][4], bl[2][4];
            #pragma unroll
            for (int i = 0; i < 4; i++) ldsm_x4(base + aoff[i] + ks * 32, ah[i]);
            #pragma unroll
            for (int i = 0; i < 4; i++) ldsm_x4(base + MATB + aoff[i] + ks * 32, alr[i]);
            #pragma unroll
            for (int jj = 0; jj < 2; jj++) ldsm_x4(base + 2*MATB + boff[jj] + ks * 32, bh[jj]);
            #pragma unroll
            for (int jj = 0; jj < 2; jj++) ldsm_x4(base + 3*MATB + boff[jj] + ks * 32, bl[jj]);

            #pragma unroll
            for (int i = 0; i < 4; i++) {
                #pragma unroll
                for (int j = 0; j < 4; j++) {
                    uint32_t b0h = bh[j >> 1][(j & 1) * 2], b1h = bh[j >> 1][(j & 1) * 2 + 1];
                    uint32_t b0l = bl[j >> 1][(j & 1) * 2], b1l = bl[j >> 1][(j & 1) * 2 + 1];
                    mma_bf16(acc[i][j], ah[i],  b0h, b1h);
                    mma_bf16(acc[i][j], ah[i],  b0l, b1l);
                    mma_bf16(acc[i][j], alr[i], b0h, b1h);
                }
            }
        }

        if (c + 1 < nC) {
            char* b = sm + ((c + 1) & 1) * BUFB;
            *reinterpret_cast<uint4*>(b + so0)          = f0;
            *reinterpret_cast<uint4*>(b + so1)          = f1;
            *reinterpret_cast<uint4*>(b + MATB + so0)   = f2;
            *reinterpret_cast<uint4*>(b + MATB + so1)   = f3;
            *reinterpret_cast<uint4*>(b + 2*MATB + so0) = f4;
            *reinterpret_cast<uint4*>(b + 2*MATB + so1) = f5;
            *reinterpret_cast<uint4*>(b + 3*MATB + so0) = f6;
            *reinterpret_cast<uint4*>(b + 3*MATB + so1) = f7;
            __syncthreads();
        }
    }

    int r = lane >> 2, cp = (lane & 3) * 2;
    #pragma unroll
    for (int i = 0; i < 4; i++) {
        int gr = m0 + wm * 64 + i * 16 + r;
        #pragma unroll
        for (int j = 0; j < 4; j++) {
            int gc = n0 + wc * 32 + j * 8 + cp;
            float b0 = bias ? bias[gc] : 0.f;
            float b1 = bias ? bias[gc + 1] : 0.f;
            float2 v0 = make_float2(acc[i][j][0] + b0, acc[i][j][1] + b1);
            float2 v1 = make_float2(acc[i][j][2] + b0, acc[i][j][3] + b1);
            *reinterpret_cast<float2*>(C + (size_t)gr * N + gc) = v0;
            *reinterpret_cast<float2*>(C + (size_t)(gr + 8) * N + gc) = v1;
        }
    }
}

// ============================================================
// 5) HMMA bf16x3 flash attention
//    q-tile 128 (8 warps x 16 rows), k-tile 64, smem overlay 36KB
// ============================================================
#define APADB 144          // bytes per 64-col row (72 bf16)
#define QMAT 18432         // 128 * 144
#define KMAT 9216          // 64 * 144

__global__ __launch_bounds__(256) void attn_mma(__nv_bfloat16* __restrict__ oh,
                                                __nv_bfloat16* __restrict__ ol)
{
    __shared__ __align__(16) char smb[2 * QMAT];
    uint32_t sb = smem_u32(smb);
    int qt = (int)gridDim.x - 1 - (int)blockIdx.x;   // heavy first
    int bh = blockIdx.y;
    int b = bh >> 3, hd = bh & 7;
    int q0 = qt * 128;
    int t = threadIdx.x, lane = t & 31, w = t >> 5;
    size_t base = (size_t)bh * LL * 64;

    // --- load Q tile (hi/lo) ---
    #pragma unroll
    for (int i = 0; i < 4; i++) {
        int ch = t + i * 256;
        int r = ch >> 3, d0 = (ch & 7) * 8;
        size_t g = base + (size_t)(q0 + r) * 64 + d0;
        *reinterpret_cast<uint4*>(smb + r * APADB + d0 * 2)        = *reinterpret_cast<const uint4*>(g_Qh + g);
        *reinterpret_cast<uint4*>(smb + QMAT + r * APADB + d0 * 2) = *reinterpret_cast<const uint4*>(g_Ql + g);
    }
    __syncthreads();

    uint32_t qfh[4][4], qfl[4][4];
    #pragma unroll
    for (int kc = 0; kc < 4; kc++) {
        uint32_t addr = sb + (w * 16 + (lane & 15)) * APADB + (kc * 16 + (lane >> 4) * 8) * 2;
        ldsm_x4(addr, qfh[kc]);
        ldsm_x4(addr + QMAT, qfl[kc]);
    }
    __syncthreads();

    float oacc[8][4];
    #pragma unroll
    for (int j = 0; j < 8; j++)
        #pragma unroll
        for (int q = 0; q < 4; q++) oacc[j][q] = 0.f;
    float m_run[2] = {-1e30f, -1e30f};
    float l_run[2] = {0.f, 0.f};
    float slope = exp2f(-(float)(hd + 1));
    int rbase = q0 + w * 16 + (lane >> 2);
    int imaxw = q0 + w * 16 + 15;
    int ktmax = 2 * qt + 1;

    for (int kt = 0; kt <= ktmax; kt++) {
        int k0 = kt * 64;
        __syncthreads();
        // load K/V hi/lo tiles: Kh@0 Kl@9216 Vh@18432 Vl@27648
        #pragma unroll
        for (int i = 0; i < 2; i++) {
            int ch = t + i * 256;
            int r = ch >> 3, d0 = (ch & 7) * 8;
            size_t g = base + (size_t)(k0 + r) * 64 + d0;
            uint32_t so = r * APADB + d0 * 2;
            *reinterpret_cast<uint4*>(smb + so)            = *reinterpret_cast<const uint4*>(g_Kh + g);
            *reinterpret_cast<uint4*>(smb + KMAT + so)     = *reinterpret_cast<const uint4*>(g_Kl + g);
            *reinterpret_cast<uint4*>(smb + 2 * KMAT + so) = *reinterpret_cast<const uint4*>(g_Vh + g);
            *reinterpret_cast<uint4*>(smb + 3 * KMAT + so) = *reinterpret_cast<const uint4*>(g_Vl + g);
        }
        __syncthreads();
        if (k0 > imaxw) continue;      // fully masked for this warp

        // --- S = Q K^T (x3) ---
        float s[8][4];
        #pragma unroll
        for (int j = 0; j < 8; j++)
            #pragma unroll
            for (int q = 0; q < 4; q++) s[j][q] = 0.f;

        #pragma unroll
        for (int kc = 0; kc < 4; kc++) {
            #pragma unroll
            for (int g = 0; g < 4; g++) {
                uint32_t kh4[4], kl4[4];
                uint32_t addr = sb + (g * 16 + (lane >> 4) * 8 + (lane & 7)) * APADB
                              + (kc * 16 + ((lane >> 3) & 1) * 8) * 2;
                ldsm_x4(addr, kh4);
                ldsm_x4(addr + KMAT, kl4);
                #pragma unroll
                for (int hf = 0; hf < 2; hf++) {
                    int jn = g * 2 + hf;
                    mma_bf16(s[jn], qfh[kc], kh4[hf * 2], kh4[hf * 2 + 1]);
                    mma_bf16(s[jn], qfh[kc], kl4[hf * 2], kl4[hf * 2 + 1]);
                    mma_bf16(s[jn], qfl[kc], kh4[hf * 2], kh4[hf * 2 + 1]);
                }
            }
        }

        // --- mask + online softmax ---
        float mnew[2] = {m_run[0], m_run[1]};
        #pragma unroll
        for (int jn = 0; jn < 8; jn++) {
            #pragma unroll
            for (int q = 0; q < 4; q++) {
                int hf = q >> 1;
                int i = rbase + hf * 8;
                int j = k0 + jn * 8 + (lane & 3) * 2 + (q & 1);
                float v = s[jn][q] * 0.125f + slope * (float)j;
                if (j > i) v = -1e30f;
                s[jn][q] = v;
                mnew[hf] = fmaxf(mnew[hf], v);
            }
        }
        #pragma unroll
        for (int hf = 0; hf < 2; hf++) {
            mnew[hf] = fmaxf(mnew[hf], __shfl_xor_sync(0xffffffffu, mnew[hf], 1));
            mnew[hf] = fmaxf(mnew[hf], __shfl_xor_sync(0xffffffffu, mnew[hf], 2));
        }
        float sc[2];
        #pragma unroll
        for (int hf = 0; hf < 2; hf++) {
            sc[hf] = __expf(m_run[hf] - mnew[hf]);
            m_run[hf] = mnew[hf];
            l_run[hf] *= sc[hf];
        }
        #pragma unroll
        for (int jn = 0; jn < 8; jn++) {
            #pragma unroll
            for (int q = 0; q < 4; q++) {
                int hf = q >> 1;
                float p = __expf(s[jn][q] - mnew[hf]);
                s[jn][q] = p;
                l_run[hf] += p;
            }
        }
        #pragma unroll
        for (int jn = 0; jn < 8; jn++) {
            #pragma unroll
            for (int q = 0; q < 4; q++) oacc[jn][q] *= sc[q >> 1];
        }

        // --- O += P V (x3) ---
        #pragma unroll
        for (int kc = 0; kc < 4; kc++) {
            uint32_t pah[4], pal[4];
            #pragma unroll
            for (int half = 0; half < 2; half++) {       // frag slots (r / r+8)
                #pragma unroll
                for (int sub = 0; sub < 2; sub++) {      // jn = 2kc + sub
                    float a = s[2 * kc + sub][half * 2];
                    float bb = s[2 * kc + sub][half * 2 + 1];
                    __nv_bfloat162 hp = __floats2bfloat162_rn(a, bb);
                    float ra = a - __low2float(hp);
                    float rb = bb - __high2float(hp);
                    __nv_bfloat162 lp = __floats2bfloat162_rn(ra, rb);
                    pah[sub * 2 + half] = bf2bits(hp);
                    pal[sub * 2 + half] = bf2bits(lp);
                }
            }
            #pragma unroll
            for (int g = 0; g < 4; g++) {
                uint32_t vh4[4], vl4[4];
                uint32_t addr = sb + 2 * KMAT
                              + (kc * 16 + ((lane >> 3) & 1) * 8 + (lane & 7)) * APADB
                              + (g * 16 + (lane >> 4) * 8) * 2;
                ldsm_x4_t(addr, vh4);
                ldsm_x4_t(addr + KMAT, vl4);
                #pragma unroll
                for (int hf = 0; hf < 2; hf++) {
                    int dn = g * 2 + hf;
                    mma_bf16(oacc[dn], pah, vh4[hf * 2], vh4[hf * 2 + 1]);
                    mma_bf16(oacc[dn], pah, vl4[hf * 2], vl4[hf * 2 + 1]);
                    mma_bf16(oacc[dn], pal, vh4[hf * 2], vh4[hf * 2 + 1]);
                }
            }
        }
    }

    // --- epilogue ---
    float inv[2];
    #pragma unroll
    for (int hf = 0; hf < 2; hf++) {
        float lr = l_run[hf];
        lr += __shfl_xor_sync(0xffffffffu, lr, 1);
        lr += __shfl_xor_sync(0xffffffffu, lr, 2);
        inv[hf] = 1.f / lr;
    }
    #pragma unroll
    for (int jn = 0; jn < 8; jn++) {
        int d = hd * 64 + jn * 8 + (lane & 3) * 2;
        #pragma unroll
        for (int hf = 0; hf < 2; hf++) {
            int row = q0 + w * 16 + (lane >> 2) + hf * 8;
            float v0 = oacc[jn][hf * 2] * inv[hf];
            float v1 = oacc[jn][hf * 2 + 1] * inv[hf];
            __nv_bfloat162 hp = __floats2bfloat162_rn(v0, v1);
            __nv_bfloat162 lp = __floats2bfloat162_rn(v0 - __low2float(hp),
                                                      v1 - __high2float(hp));
            size_t off = (size_t)(b * LL + row) * VP + d;
            *reinterpret_cast<__nv_bfloat162*>(g_A2h + off) = hp;
            *reinterpret_cast<__nv_bfloat162*>(g_A2l + off) = lp;
        }
    }
    (void)oh; (void)ol;
}

// ============================================================
// 6) exact GELU -> hi/lo bf16 into A2 cols [512, 2560)
// ============================================================
__global__ __launch_bounds__(256) void gelu_kernel()
{
    int idx = blockIdx.x * blockDim.x + threadIdx.x;
    const int total = TOK * 2048 / 4;
    for (int i = idx; i < total; i += gridDim.x * blockDim.x) {
        int tok = i >> 9;
        int e4 = i & 511;
        float4 v = *reinterpret_cast<const float4*>(g_proj + (size_t)tok * QKVP + 1536 + 4 * e4);
        v.x = v.x * normcdff(v.x);
        v.y = v.y * normcdff(v.y);
        v.z = v.z * normcdff(v.z);
        v.w = v.w * normcdff(v.w);
        __nv_bfloat162 h0 = __floats2bfloat162_rn(v.x, v.y);
        __nv_bfloat162 h1 = __floats2bfloat162_rn(v.z, v.w);
        __nv_bfloat162 l0 = __floats2bfloat162_rn(v.x - __low2float(h0), v.y - __high2float(h0));
        __nv_bfloat162 l1 = __floats2bfloat162_rn(v.z - __low2float(h1), v.w - __high2float(h1));
        size_t base = (size_t)tok * VP + 512 + 4 * e4;
        *reinterpret_cast<__nv_bfloat162*>(g_A2h + base)     = h0;
        *reinterpret_cast<__nv_bfloat162*>(g_A2h + base + 2) = h1;
        *reinterpret_cast<__nv_bfloat162*>(g_A2l + base)     = l0;
        *reinterpret_cast<__nv_bfloat162*>(g_A2l + base + 2) = l1;
    }
}

// ============================================================
// launch
// ============================================================
extern "C" void kernel_launch(void* const* d_in, const int* in_sizes, int n_in,
                              void* d_out, int out_size)
{
    const float* x     = (const float*)d_in[0];
    const float* gamma = (const float*)d_in[1];
    const float* beta  = (const float*)d_in[2];
    const float* w_in  = (const float*)d_in[3];
    const float* w_out = (const float*)d_in[4];
    const float* b_out = (const float*)d_in[5];
    float* out = (float*)d_out;

    float *xt, *proj;
    __nv_bfloat16 *a1h, *a1l, *b1h, *b1l, *a2h, *a2l, *b2h, *b2l;
    cudaGetSymbolAddress((void**)&xt,   g_xt);
    cudaGetSymbolAddress((void**)&proj, g_proj);
    cudaGetSymbolAddress((void**)&a1h,  g_A1h);
    cudaGetSymbolAddress((void**)&a1l,  g_A1l);
    cudaGetSymbolAddress((void**)&b1h,  g_B1h);
    cudaGetSymbolAddress((void**)&b1l,  g_B1l);
    cudaGetSymbolAddress((void**)&a2h,  g_A2h);
    cudaGetSymbolAddress((void**)&a2l,  g_A2l);
    cudaGetSymbolAddress((void**)&b2h,  g_B2h);
    cudaGetSymbolAddress((void**)&b2l,  g_B2l);

    cudaFuncSetAttribute(gemm_tc, cudaFuncAttributeMaxDynamicSharedMemorySize, GEMM_SMEM);

    transcvt_kernel<<<dim3(QKVP / 32, HID / 32), 256>>>(w_in, b1h, b1l, HID, QKVP);
    transcvt_kernel<<<dim3(HID / 32, VP / 32), 256>>>(w_out, b2h, b2l, VP, HID);

    ln_kernel<<<TOK, 128>>>(x, gamma, beta);
    scan_kernel<<<32, 128>>>();
    cvt_kernel<<<(TOK * HID / 4 + 255) / 256, 256>>>(xt, a1h, a1l, TOK * HID / 4);

    gemm_tc<<<dim3(QKVP / 128, TOK / 128), 256, GEMM_SMEM>>>(
        a1h, a1l, b1h, b1l, nullptr, proj, TOK, QKVP, HID);

    qkv_cvt<<<dim3(TOK * HID / 4 / 256, 3), 256>>>();
    attn_mma<<<dim3(LL / 128, BB * HH), 256>>>(a2h, a2l);
    gelu_kernel<<<2048, 256>>>();

    gemm_tc<<<dim3(HID / 128, TOK / 128), 256, GEMM_SMEM>>>(
        a2h, a2l, b2h, b2l, b_out, out, TOK, HID, VP);
}